// round 12
// baseline (speedup 1.0000x reference)
#include <cuda_runtime.h>

#define T_STEPS 512
#define BATCH   2048
#define IN_DIM  28
#define HID     198
#define OUT_DIM 10

#define BBLK     16
#define NBLOCKS  (BATCH / BBLK)   // 128
#define NTHREADS 384              // 12 warps = 3 k-split (kh) x 4 j-groups (jw)

#define KPAD 200                  // recurrent k padded to 200 (50 quads), pad = 0
#define HSTR 200                  // 200*4B row: rows {u,u+4,..} -> banks 8u mod 32, conflict-free; 16B aligned
#define USTR 36                   // U_s / x_s row stride

// shared layout (floats)
#define H_S_OFF   0
#define U_S_OFF   (HID * HSTR)                 // 39600
#define HST_S_OFF (U_S_OFF + HID * USTR)       // 46728
#define X_S_OFF   (HST_S_OFF + BBLK * HSTR)    // 49928
#define RED_S_OFF (X_S_OFF + BBLK * USTR)      // 50504
#define SMEM_FLOATS (RED_S_OFF + 2 * 4 * 32 * 28)  // 57672 floats = 230,688 B (< 232,448 cap)

// k-split of the 57 quad-equivalents: kh0: rec[0,19); kh1: rec[19,38); kh2: rec[38,50) + input(7)
#define KH0_END 19
#define KH1_END 38

typedef unsigned long long ull;

// packed dual-fp32 FMA: d.lo += a.lo*b.lo ; d.hi += a.hi*b.hi
__device__ __forceinline__ void fma2(ull& d, ull a, ull b) {
    asm("fma.rn.f32x2 %0, %1, %2, %0;" : "+l"(d) : "l"(a), "l"(b));
}

// branchless fast tanh (rel err ~1e-7)
__device__ __forceinline__ float fast_tanh(float x) {
    float ax = fabsf(x);
    float t  = __expf(-2.0f * ax);
    float r  = __fdividef(1.0f - t, 1.0f + t);
    return copysignf(r, x);
}

// one k-quad: 4 row-vectors x 7 weight rows, packed FMAs (11 LDS.128, 56 fma2)
template<int STRIDE>
__device__ __forceinline__ void quad_fma(
    ull (&acc)[4][7],
    const float* __restrict__ Wb, const float* __restrict__ vb,
    const int (&jj)[7], int u, int kq)
{
    ulonglong2 hv[4];
#pragma unroll
    for (int i = 0; i < 4; i++)
        hv[i] = *reinterpret_cast<const ulonglong2*>(vb + (u + 4*i) * STRIDE + kq * 4);
#pragma unroll
    for (int m = 0; m < 7; m++) {
        ulonglong2 wv = *reinterpret_cast<const ulonglong2*>(Wb + jj[m] * STRIDE + kq * 4);
#pragma unroll
        for (int i = 0; i < 4; i++) {
            fma2(acc[i][m], hv[i].x, wv.x);
            fma2(acc[i][m], hv[i].y, wv.y);
        }
    }
}

__global__ __launch_bounds__(NTHREADS, 1)
void SimpleRNN_kernel(const float* __restrict__ x, const float* __restrict__ H,
                      const float* __restrict__ U, const float* __restrict__ A,
                      const float* __restrict__ bvec, const float* __restrict__ cvec,
                      float* __restrict__ out)
{
    extern __shared__ float sm[];
    float* sm_H   = sm + H_S_OFF;    // [HID][HSTR], k-cols 198..199 zero
    float* sm_U   = sm + U_S_OFF;    // [HID][USTR] transposed U, k-cols 28..35 zero
    float* sm_h   = sm + HST_S_OFF;  // [16][HSTR], pad cols stay zero forever
    float* sm_x   = sm + X_S_OFF;    // [16][USTR]
    float* sm_red = sm + RED_S_OFF;  // [2 ranks][4 jw][32 lanes][28]

    const int tid = threadIdx.x;
    const int b0  = blockIdx.x * BBLK;

    // ---- one-time weight staging ----
    for (int i = tid; i < HID * HSTR; i += NTHREADS) {
        int j = i / HSTR, k = i - j * HSTR;
        sm_H[i] = (k < HID) ? H[j * HID + k] : 0.f;
    }
    for (int i = tid; i < HID * USTR; i += NTHREADS) {
        int j = i / USTR, k = i - j * USTR;
        sm_U[i] = (k < IN_DIM) ? U[k * HID + j] : 0.f;
    }
    for (int i = tid; i < BBLK * HSTR; i += NTHREADS)
        sm_h[i] = 0.f;                                 // h0 = 0

    // ---- lane decomposition ----
    // warp: kh = wid>>2 (k-split 0..2), jw = wid&3 (j-group 0..3)
    // lane: u = row-lane (0..3), v = j-lane (0..7)
    // thread tile: rows {u, u+4, u+8, u+12} x 7 j,  j = jw*56 + v*7 + m
    const int wid  = tid >> 5;
    const int lane = tid & 31;
    const int kh   = wid >> 2;
    const int jw   = wid & 3;
    const int u    = lane & 3;
    const int v    = lane >> 2;

    int   jj[7];
    float bias[7];
    bool  jv[7];
#pragma unroll
    for (int m = 0; m < 7; m++) {
        int j = jw * 56 + v * 7 + m;
        jv[m]   = (j < HID);
        jj[m]   = jv[m] ? j : 0;          // clamp keeps reads in-bounds
        bias[m] = bvec[jj[m]];
    }
    // red addressing: slot(rank) = ((rank*4 + jw)*32 + lane)*28 + p
    float* red0 = sm_red + ((0 * 4 + jw) * 32 + lane) * 28;
    float* red1 = sm_red + ((1 * 4 + jw) * 32 + lane) * 28;

    // x prefetch bookkeeping: 448 floats/step; i0 = tid (all), i1 = tid+384 (tid<64)
    const int  i0   = tid;
    const int  i1   = tid + NTHREADS;
    const bool has2 = (i1 < BBLK * IN_DIM);
    const int  d0   = (i0 / IN_DIM) * USTR + (i0 % IN_DIM);
    const int  d1   = has2 ? (i1 / IN_DIM) * USTR + (i1 % IN_DIM) : 0;

    const float* gx = x + (size_t)b0 * IN_DIM;   // advances by BATCH*IN_DIM each step
    float xr0 = gx[i0];
    float xr1 = has2 ? gx[i1] : 0.f;

    __syncthreads();

    for (int t = 0; t < T_STEPS; t++) {
        // stage x(t) from prefetched registers
        sm_x[d0] = xr0;
        if (has2) sm_x[d1] = xr1;
        __syncthreads();   // B: x(t) + h(t-1) visible

        // issue x(t+1) prefetch early (hidden under GEMM)
        if (t + 1 < T_STEPS) {
            const float* gxn = gx + BATCH * IN_DIM;
            xr0 = gxn[i0];
            if (has2) xr1 = gxn[i1];
        }
        gx += BATCH * IN_DIM;

        ull acc[4][7];
#pragma unroll
        for (int i = 0; i < 4; i++)
#pragma unroll
            for (int m = 0; m < 7; m++) acc[i][m] = 0ull;

        if (kh == 0) {
#pragma unroll 2
            for (int kq = 0; kq < KH0_END; kq++)
                quad_fma<HSTR>(acc, sm_H, sm_h, jj, u, kq);
        } else if (kh == 1) {
#pragma unroll 2
            for (int kq = KH0_END; kq < KH1_END; kq++)
                quad_fma<HSTR>(acc, sm_H, sm_h, jj, u, kq);
        } else {
#pragma unroll 2
            for (int kq = KH1_END; kq < KPAD / 4; kq++)
                quad_fma<HSTR>(acc, sm_H, sm_h, jj, u, kq);
            // input projection: K = 28 -> 7 quads
#pragma unroll
            for (int kq = 0; kq < IN_DIM / 4; kq++)
                quad_fma<USTR>(acc, sm_U, sm_x, jj, u, kq);
        }

        // horizontal sums
        float s[28];
#pragma unroll
        for (int i = 0; i < 4; i++)
#pragma unroll
            for (int m = 0; m < 7; m++) {
                float2 a = *reinterpret_cast<float2*>(&acc[i][m]);
                s[i * 7 + m] = a.x + a.y;
            }

        // write partials for slots this warp does NOT finalize
        // slot p is finalized by kh_f = p%3; writer rank = (kh - kh_f + 3)%3 - 1
#pragma unroll
        for (int p = 0; p < 28; p++) {
            int f = p % 3;
            if (f != kh) {
                int rank = ((kh - f + 3) % 3) - 1;   // 0 or 1
                (rank == 0 ? red0 : red1)[p] = s[p];
            }
        }

        __syncthreads();   // C: partials visible; all h/x reads done

        // finalize this warp's slots: sum partials, tanh, store h
#pragma unroll
        for (int p = 0; p < 28; p++) {
            if (p % 3 == kh) {
                int i = p / 7, m = p % 7;
                float val = s[p] + red0[p] + red1[p] + bias[m];
                float hv  = fast_tanh(val);
                if (jv[m])
                    sm_h[(u + 4 * i) * HSTR + jj[m]] = hv;
            }
        }
        // next iteration's barrier B orders these stores before the reads
    }
    __syncthreads();

    // ---- output projection: out[b][o] = h[b] . A[o] + c[o]  (16 x 10 per block) ----
    if (tid < BBLK * OUT_DIM) {
        int bb = tid / OUT_DIM;
        int o  = tid - bb * OUT_DIM;
        float sacc = cvec[o];
        const float* hrow = sm_h + bb * HSTR;
        const float* arow = A + o * HID;
#pragma unroll 4
        for (int j = 0; j < HID; j++)
            sacc += hrow[j] * arow[j];
        out[(b0 + bb) * OUT_DIM + o] = sacc;
    }
}

extern "C" void kernel_launch(void* const* d_in, const int* in_sizes, int n_in,
                              void* d_out, int out_size)
{
    const float *x = nullptr, *H = nullptr, *U = nullptr, *A = nullptr, *b = nullptr, *c = nullptr;
    for (int i = 0; i < n_in; i++) {
        const float* p = (const float*)d_in[i];
        switch (in_sizes[i]) {
            case T_STEPS * BATCH * IN_DIM: x = p; break;
            case HID * HID:                H = p; break;
            case IN_DIM * HID:             U = p; break;
            case OUT_DIM * HID:            A = p; break;
            case HID:                      b = p; break;
            case OUT_DIM:                  c = p; break;
            default: break;
        }
    }
    float* out = (float*)d_out;

    size_t smem_bytes = SMEM_FLOATS * sizeof(float);   // 230,688 B
    cudaFuncSetAttribute(SimpleRNN_kernel,
                         cudaFuncAttributeMaxDynamicSharedMemorySize, (int)smem_bytes);

    SimpleRNN_kernel<<<NBLOCKS, NTHREADS, smem_bytes>>>(x, H, U, A, b, c, out);
}